// round 14
// baseline (speedup 1.0000x reference)
#include <cuda_runtime.h>

#define N_NODES 100000
#define E_EDGES 1200000
#define DIM 64
#define EPS_BN 1e-5f
#define NB_N 391      // ceil(N_NODES/256)
#define NB_E4 1172    // ceil(E_EDGES/1024)
#define NWARPS_G 6250 // N_NODES/16
#define NB_G 782      // ceil(6250/8)
#define NB_T 6250     // node-tile blocks (16 nodes each)
#define SH_STRIDE 68  // padded row stride (floats): conflict-free MMA A-reads

// ---------------- scratch (static device globals; no allocation) ----------------
__device__ int   g_cnt[N_NODES];        // zero at load; re-zeroed by k_scatter2 each launch
__device__ int   g_part[NB_N];
__device__ int   g_rowptr[N_NODES + 1];
__device__ int   g_rank[E_EDGES];
__device__ int   g_csr_src[E_EDGES];
__device__ float g_Y[(size_t)N_NODES * DIM];
__device__ float g_Z[(size_t)N_NODES * DIM];
__device__ float g_Y2[(size_t)N_NODES * DIM];
__device__ float g_Z2[(size_t)N_NODES * DIM];
// packed B fragments: [pair][ (nt*8+ks)*128 + lane*4 + {hi0,hi1,lo0,lo1} ]
__device__ float g_Bpack[2][16 * 8 * 32 * 4];
__device__ float g_BpackH[4 * 8 * 32 * 4];   // head W1 (32x64)

// ---------------- tf32 helpers ----------------
__device__ __forceinline__ unsigned cvt_tf32(float x) {
    unsigned r;
    asm("cvt.rna.tf32.f32 %0, %1;" : "=r"(r) : "f"(x));
    return r;
}
__device__ __forceinline__ void mma_tf32(float* c, const unsigned* a, unsigned b0, unsigned b1) {
    asm("mma.sync.aligned.m16n8k8.row.col.f32.tf32.tf32.f32 "
        "{%0,%1,%2,%3}, {%4,%5,%6,%7}, {%8,%9}, {%0,%1,%2,%3};"
        : "+f"(c[0]), "+f"(c[1]), "+f"(c[2]), "+f"(c[3])
        : "r"(a[0]), "r"(a[1]), "r"(a[2]), "r"(a[3]), "r"(b0), "r"(b1));
}

// ---------------- prepack W fragments (hi/lo tf32): 2 layer pairs + head ----------------
__global__ __launch_bounds__(256) void k_prepack(const float* __restrict__ Wl1,
                                                 const float* __restrict__ Wr1,
                                                 const float* __restrict__ Wl2,
                                                 const float* __restrict__ Wr2,
                                                 const float* __restrict__ mW1) {
    int b = blockIdx.x;
    int t = threadIdx.x;
    if (b < 2) {
        const float* Wl = b ? Wl2 : Wl1;
        const float* Wr = b ? Wr2 : Wr1;
        for (int idx = t; idx < 4096; idx += 256) {
            int tile = idx >> 5, lane = idx & 31;
            int nt = tile >> 3, ks = tile & 7;
            int n = nt * 8 + (lane >> 2);
            int k = ks * 8 + (lane & 3);
            const float* W = (n < 64) ? Wl : Wr;
            int nn = n & 63;
            float w0 = W[nn * 64 + k];
            float w1 = W[nn * 64 + k + 4];
            unsigned h0 = cvt_tf32(w0), h1 = cvt_tf32(w1);
            unsigned l0 = cvt_tf32(w0 - __uint_as_float(h0));
            unsigned l1 = cvt_tf32(w1 - __uint_as_float(h1));
            ((float4*)(g_Bpack[b]))[idx] =
                make_float4(__uint_as_float(h0), __uint_as_float(h1),
                            __uint_as_float(l0), __uint_as_float(l1));
        }
    } else {
        for (int idx = t; idx < 1024; idx += 256) {   // 32 tiles (4 nt x 8 ks)
            int tile = idx >> 5, lane = idx & 31;
            int nt = tile >> 3, ks = tile & 7;
            int n = nt * 8 + (lane >> 2);             // 0..31 rows of mW1
            int k = ks * 8 + (lane & 3);
            float w0 = mW1[n * 64 + k];
            float w1 = mW1[n * 64 + k + 4];
            unsigned h0 = cvt_tf32(w0), h1 = cvt_tf32(w1);
            unsigned l0 = cvt_tf32(w0 - __uint_as_float(h0));
            unsigned l1 = cvt_tf32(w1 - __uint_as_float(h1));
            ((float4*)g_BpackH)[idx] =
                make_float4(__uint_as_float(h0), __uint_as_float(h1),
                            __uint_as_float(l0), __uint_as_float(l1));
        }
    }
}

// ---------------- layer-1 TC GEMM pair: [Y|Z] = X @ [Wl|Wr]^T, 3xTF32 ----------------
__global__ __launch_bounds__(256) void k_gemm_tc(const float* __restrict__ X,
                                                 const float* __restrict__ pack,
                                                 float* __restrict__ Y,
                                                 float* __restrict__ Z) {
    int w = (blockIdx.x * 256 + threadIdx.x) >> 5;
    int lane = threadIdx.x & 31;
    if (w >= NWARPS_G) return;

    int g = lane >> 2;
    int tg = lane & 3;
    int r0 = w * 16 + g;

    float c[16][4];
#pragma unroll
    for (int nt = 0; nt < 16; nt++) {
        c[nt][0] = 0.f; c[nt][1] = 0.f; c[nt][2] = 0.f; c[nt][3] = 0.f;
    }

    const float4* bp = (const float4*)pack;

#pragma unroll
    for (int ks = 0; ks < 8; ks++) {
        int k = ks * 8 + tg;
        float a00 = X[(size_t)r0 * 64 + k];
        float a10 = X[(size_t)(r0 + 8) * 64 + k];
        float a01 = X[(size_t)r0 * 64 + k + 4];
        float a11 = X[(size_t)(r0 + 8) * 64 + k + 4];

        unsigned ah[4], al[4];
        ah[0] = cvt_tf32(a00); al[0] = cvt_tf32(a00 - __uint_as_float(ah[0]));
        ah[1] = cvt_tf32(a10); al[1] = cvt_tf32(a10 - __uint_as_float(ah[1]));
        ah[2] = cvt_tf32(a01); al[2] = cvt_tf32(a01 - __uint_as_float(ah[2]));
        ah[3] = cvt_tf32(a11); al[3] = cvt_tf32(a11 - __uint_as_float(ah[3]));

#pragma unroll
        for (int nt = 0; nt < 16; nt++) {
            float4 b = bp[(nt * 8 + ks) * 32 + lane];
            mma_tf32(c[nt], ah, __float_as_uint(b.x), __float_as_uint(b.y));
            mma_tf32(c[nt], ah, __float_as_uint(b.z), __float_as_uint(b.w));
            mma_tf32(c[nt], al, __float_as_uint(b.x), __float_as_uint(b.y));
        }
    }

#pragma unroll
    for (int nt = 0; nt < 16; nt++) {
        int n0 = nt * 8 + 2 * tg;
        float* O = (nt < 8) ? Y : Z;
        int col = n0 & 63;
        ((float2*)(O + (size_t)r0 * 64 + col))[0] = make_float2(c[nt][0], c[nt][1]);
        ((float2*)(O + (size_t)(r0 + 8) * 64 + col))[0] = make_float2(c[nt][2], c[nt][3]);
    }
}

// ---------------- CSR build ----------------
// ILP-4 histogram; rank = atomicAdd return value (single atomic per edge)
__global__ __launch_bounds__(256) void k_hist(const int* __restrict__ ei) {
    int base = blockIdx.x * 1024 + threadIdx.x;
    int d[4], e[4];
#pragma unroll
    for (int u = 0; u < 4; u++) {
        e[u] = base + u * 256;
        d[u] = (e[u] < E_EDGES) ? ei[E_EDGES + e[u]] : -1;
    }
#pragma unroll
    for (int u = 0; u < 4; u++)
        if ((unsigned)d[u] < N_NODES)
            g_rank[e[u]] = atomicAdd(&g_cnt[d[u]], 1);
}

// per-block sums of 256 counters (coalesced reads, no atomics)
__global__ __launch_bounds__(256) void k_blocksum() {
    __shared__ int sc[256];
    int t = threadIdx.x;
    int i = blockIdx.x * 256 + t;
    int v = (i < N_NODES) ? g_cnt[i] : 0;
    sc[t] = v;
    __syncthreads();
    for (int off = 128; off > 0; off >>= 1) {
        if (t < off) sc[t] += sc[t + off];
        __syncthreads();
    }
    if (t == 0) g_part[blockIdx.x] = sc[0];
}

// scatter with inline lookback over g_part; also resets g_cnt for the next launch
__global__ __launch_bounds__(256) void k_scatter2() {
    __shared__ int sc[256];
    __shared__ int sbase[8];
    int t = threadIdx.x;
    int b = blockIdx.x;

    int acc = 0;
    for (int i = t; i < b; i += 256) acc += g_part[i];
#pragma unroll
    for (int o = 16; o > 0; o >>= 1) acc += __shfl_down_sync(0xffffffffu, acc, o);
    if ((t & 31) == 0) sbase[t >> 5] = acc;

    int i = b * 256 + t;
    int v = (i < N_NODES) ? g_cnt[i] : 0;
    sc[t] = v;
    __syncthreads();

    int base = 0;
#pragma unroll
    for (int w = 0; w < 8; w++) base += sbase[w];

    for (int off = 1; off < 256; off <<= 1) {
        int u = (t >= off) ? sc[t - off] : 0;
        __syncthreads();
        sc[t] += u;
        __syncthreads();
    }
    if (i < N_NODES) {
        g_rowptr[i] = base + sc[t] - v;
        g_cnt[i] = 0;   // self-clean: deterministic zero state for every launch
    }
    if (b == NB_N - 1 && t == 255) g_rowptr[N_NODES] = base + sc[255];
}

// atomic-free fill: pos = rowptr[dst] + rank
__global__ __launch_bounds__(256) void k_fill(const int* __restrict__ ei) {
    int base = blockIdx.x * 1024 + threadIdx.x;
#pragma unroll
    for (int u = 0; u < 4; u++) {
        int e = base + u * 256;
        if (e < E_EDGES) {
            int src = ei[e];
            int dst = ei[E_EDGES + e];
            if ((unsigned)dst < N_NODES && (unsigned)src < N_NODES)
                g_csr_src[g_rowptr[dst] + g_rank[e]] = src;
        }
    }
}

// ---------------- half-list gather (float2/lane, stride-2 edges starting at r0+half) ----------------
__device__ __forceinline__ void gather_half(const float* __restrict__ Y, int r0, int r1,
                                            int half, int lane, float& ax, float& ay) {
    const float2* Y2 = (const float2*)Y;
    ax = 0.f; ay = 0.f;
    int e = r0 + half;
    for (; e + 6 < r1; e += 8) {       // 4 edges per iter (stride 2)
        int s0 = g_csr_src[e];
        int s1 = g_csr_src[e + 2];
        int s2 = g_csr_src[e + 4];
        int s3 = g_csr_src[e + 6];
        float2 v0 = Y2[(size_t)s0 * 32 + lane];
        float2 v1 = Y2[(size_t)s1 * 32 + lane];
        float2 v2 = Y2[(size_t)s2 * 32 + lane];
        float2 v3 = Y2[(size_t)s3 * 32 + lane];
        ax += (v0.x + v1.x) + (v2.x + v3.x);
        ay += (v0.y + v1.y) + (v2.y + v3.y);
    }
    for (; e < r1; e += 2) {
        float2 v = Y2[(size_t)g_csr_src[e] * 32 + lane];
        ax += v.x;
        ay += v.y;
    }
}

// ---------------- BN+ReLU epilogue for lane's feature pair ----------------
__device__ __forceinline__ float2 bn_relu(float ax, float ay, float inv, int lane,
                                          const float* __restrict__ Z, int node,
                                          const float* __restrict__ bl,
                                          const float* __restrict__ gam,
                                          const float* __restrict__ bet,
                                          const float* __restrict__ mu,
                                          const float* __restrict__ var) {
    int j0 = 2 * lane, j1 = 2 * lane + 1;
    float2 z = ((const float2*)Z)[(size_t)node * 32 + lane];
    float h0 = ax * inv + bl[j0] + z.x;
    float h1 = ay * inv + bl[j1] + z.y;
    float s0 = gam[j0] * rsqrtf(var[j0] + EPS_BN);
    float s1 = gam[j1] * rsqrtf(var[j1] + EPS_BN);
    h0 = fmaxf((h0 - mu[j0]) * s0 + bet[j0], 0.f);
    h1 = fmaxf((h1 - mu[j1]) * s1 + bet[j1], 0.f);
    return make_float2(h0, h1);
}

// ---------------- fused: agg1 (2 warps/node) + layer-2 GEMM pair -> Y2, Z2 ----------------
__global__ __launch_bounds__(1024) void k_agg1_gemm2(const float* __restrict__ Y,
                                                     const float* __restrict__ Z,
                                                     const float* __restrict__ bl,
                                                     const float* __restrict__ gam,
                                                     const float* __restrict__ bet,
                                                     const float* __restrict__ mu,
                                                     const float* __restrict__ var,
                                                     const float* __restrict__ pack,
                                                     float* __restrict__ Yo,
                                                     float* __restrict__ Zo) {
    __shared__ float sH[16 * SH_STRIDE];
    __shared__ float2 sP[16 * 32];
    int tid = threadIdx.x;
    int wid = tid >> 5;
    int lane = tid & 31;
    int nl = wid >> 1;          // node within block
    int half = wid & 1;
    int base = blockIdx.x * 16;
    int node = base + nl;

    int r0 = g_rowptr[node];
    int r1 = g_rowptr[node + 1];
    float ax, ay;
    gather_half(Y, r0, r1, half, lane, ax, ay);
    if (half == 1) sP[nl * 32 + lane] = make_float2(ax, ay);
    __syncthreads();

    if (half == 0) {
        float2 p = sP[nl * 32 + lane];
        ax += p.x; ay += p.y;
        int deg = r1 - r0;
        float inv = 1.f / (float)(deg > 0 ? deg : 1);
        float2 h = bn_relu(ax, ay, inv, lane, Z, node, bl, gam, bet, mu, var);
        ((float2*)(sH + nl * SH_STRIDE))[lane] = h;
    }
    __syncthreads();

    // MMA phase: warps 0..15, warp wid computes n-tile nt=wid over the 16-row tile
    if (wid < 16) {
        int nt = wid;
        int g = lane >> 2;
        int tg = lane & 3;

        float c[4] = {0.f, 0.f, 0.f, 0.f};
        const float4* bp = (const float4*)pack;

#pragma unroll
        for (int ks = 0; ks < 8; ks++) {
            int k = ks * 8 + tg;
            float a00 = sH[g * SH_STRIDE + k];
            float a10 = sH[(g + 8) * SH_STRIDE + k];
            float a01 = sH[g * SH_STRIDE + k + 4];
            float a11 = sH[(g + 8) * SH_STRIDE + k + 4];

            unsigned ah[4], al[4];
            ah[0] = cvt_tf32(a00); al[0] = cvt_tf32(a00 - __uint_as_float(ah[0]));
            ah[1] = cvt_tf32(a10); al[1] = cvt_tf32(a10 - __uint_as_float(ah[1]));
            ah[2] = cvt_tf32(a01); al[2] = cvt_tf32(a01 - __uint_as_float(ah[2]));
            ah[3] = cvt_tf32(a11); al[3] = cvt_tf32(a11 - __uint_as_float(ah[3]));

            float4 b = bp[(nt * 8 + ks) * 32 + lane];
            mma_tf32(c, ah, __float_as_uint(b.x), __float_as_uint(b.y));
            mma_tf32(c, ah, __float_as_uint(b.z), __float_as_uint(b.w));
            mma_tf32(c, al, __float_as_uint(b.x), __float_as_uint(b.y));
        }

        float* O = (nt < 8) ? Yo : Zo;
        int col = (nt * 8 + 2 * tg) & 63;
        ((float2*)(O + (size_t)(base + g) * 64 + col))[0] = make_float2(c[0], c[1]);
        ((float2*)(O + (size_t)(base + g + 8) * 64 + col))[0] = make_float2(c[2], c[3]);
    }
}

// ---------------- fused: agg2 (2 warps/node) + MLP head -> out ----------------
__global__ __launch_bounds__(1024) void k_agg2_head(const float* __restrict__ Y,
                                                    const float* __restrict__ Z,
                                                    const float* __restrict__ bl,
                                                    const float* __restrict__ gam,
                                                    const float* __restrict__ bet,
                                                    const float* __restrict__ mu,
                                                    const float* __restrict__ var,
                                                    const float* __restrict__ packH,
                                                    const float* __restrict__ mb1,
                                                    const float* __restrict__ mW2,
                                                    const float* __restrict__ mb2,
                                                    float* __restrict__ out) {
    __shared__ float sH[16 * SH_STRIDE];
    __shared__ float2 sP[16 * 32];
    __shared__ float spart[64];
    int tid = threadIdx.x;
    int wid = tid >> 5;
    int lane = tid & 31;
    int nl = wid >> 1;
    int half = wid & 1;
    int base = blockIdx.x * 16;
    int node = base + nl;

    int r0 = g_rowptr[node];
    int r1 = g_rowptr[node + 1];
    float ax, ay;
    gather_half(Y, r0, r1, half, lane, ax, ay);
    if (half == 1) sP[nl * 32 + lane] = make_float2(ax, ay);
    __syncthreads();

    if (half == 0) {
        float2 p = sP[nl * 32 + lane];
        ax += p.x; ay += p.y;
        int deg = r1 - r0;
        float inv = 1.f / (float)(deg > 0 ? deg : 1);
        float2 h = bn_relu(ax, ay, inv, lane, Z, node, bl, gam, bet, mu, var);
        ((float2*)(sH + nl * SH_STRIDE))[lane] = h;
    }
    __syncthreads();

    if (wid < 4) {
        int nt = wid;
        int g = lane >> 2;
        int tg = lane & 3;

        float c[4] = {0.f, 0.f, 0.f, 0.f};
        const float4* bp = (const float4*)packH;

#pragma unroll
        for (int ks = 0; ks < 8; ks++) {
            int k = ks * 8 + tg;
            float a00 = sH[g * SH_STRIDE + k];
            float a10 = sH[(g + 8) * SH_STRIDE + k];
            float a01 = sH[g * SH_STRIDE + k + 4];
            float a11 = sH[(g + 8) * SH_STRIDE + k + 4];

            unsigned ah[4], al[4];
            ah[0] = cvt_tf32(a00); al[0] = cvt_tf32(a00 - __uint_as_float(ah[0]));
            ah[1] = cvt_tf32(a10); al[1] = cvt_tf32(a10 - __uint_as_float(ah[1]));
            ah[2] = cvt_tf32(a01); al[2] = cvt_tf32(a01 - __uint_as_float(ah[2]));
            ah[3] = cvt_tf32(a11); al[3] = cvt_tf32(a11 - __uint_as_float(ah[3]));

            float4 b = bp[(nt * 8 + ks) * 32 + lane];
            mma_tf32(c, ah, __float_as_uint(b.x), __float_as_uint(b.y));
            mma_tf32(c, ah, __float_as_uint(b.z), __float_as_uint(b.w));
            mma_tf32(c, al, __float_as_uint(b.x), __float_as_uint(b.y));
        }

        int j = nt * 8 + 2 * tg;
        float b1a = mb1[j], b1b = mb1[j + 1];
        float w2a = mW2[j], w2b = mW2[j + 1];
        float v0 = fmaxf(c[0] + b1a, 0.f) * w2a + fmaxf(c[1] + b1b, 0.f) * w2b;
        float v1 = fmaxf(c[2] + b1a, 0.f) * w2a + fmaxf(c[3] + b1b, 0.f) * w2b;
        v0 += __shfl_xor_sync(0xffffffffu, v0, 1);
        v0 += __shfl_xor_sync(0xffffffffu, v0, 2);
        v1 += __shfl_xor_sync(0xffffffffu, v1, 1);
        v1 += __shfl_xor_sync(0xffffffffu, v1, 2);
        int g2i = lane >> 2;
        if ((lane & 3) == 0) {
            spart[nt * 16 + g2i] = v0;
            spart[nt * 16 + g2i + 8] = v1;
        }
    }
    __syncthreads();

    if (tid < 16) {
        float s = spart[tid] + spart[16 + tid] + spart[32 + tid] + spart[48 + tid] + mb2[0];
        out[base + tid] = 1.f / (1.f + __expf(-s));
    }
}

// ---------------- launch ----------------
extern "C" void kernel_launch(void* const* d_in, const int* in_sizes, int n_in,
                              void* d_out, int out_size) {
    const float* x    = (const float*)d_in[0];
    const int*   ei   = (const int*)d_in[1];
    const float* Wl1  = (const float*)d_in[2];
    const float* bl1  = (const float*)d_in[3];
    const float* Wr1  = (const float*)d_in[4];
    const float* g1   = (const float*)d_in[5];
    const float* be1  = (const float*)d_in[6];
    const float* m1   = (const float*)d_in[7];
    const float* v1   = (const float*)d_in[8];
    const float* Wl2  = (const float*)d_in[9];
    const float* bl2  = (const float*)d_in[10];
    const float* Wr2  = (const float*)d_in[11];
    const float* g2   = (const float*)d_in[12];
    const float* be2  = (const float*)d_in[13];
    const float* m2   = (const float*)d_in[14];
    const float* v2   = (const float*)d_in[15];
    const float* mW1  = (const float*)d_in[16];
    const float* mb1  = (const float*)d_in[17];
    const float* mW2  = (const float*)d_in[18];
    const float* mb2  = (const float*)d_in[19];
    float* out = (float*)d_out;

    float* Y;  cudaGetSymbolAddress((void**)&Y, g_Y);
    float* Z;  cudaGetSymbolAddress((void**)&Z, g_Z);
    float* Y2; cudaGetSymbolAddress((void**)&Y2, g_Y2);
    float* Z2; cudaGetSymbolAddress((void**)&Z2, g_Z2);
    float* Bp; cudaGetSymbolAddress((void**)&Bp, g_Bpack);
    float* BpH; cudaGetSymbolAddress((void**)&BpH, g_BpackH);

    static cudaStream_t sb = nullptr;
    static cudaEvent_t evFork = nullptr, evJoin = nullptr;
    if (!sb) {
        cudaStreamCreateWithFlags(&sb, cudaStreamNonBlocking);
        cudaEventCreateWithFlags(&evFork, cudaEventDisableTiming);
        cudaEventCreateWithFlags(&evJoin, cudaEventDisableTiming);
    }

    // fork: CSR chain on side stream, concurrent with prepack + layer-1 GEMM
    cudaEventRecord(evFork, 0);
    cudaStreamWaitEvent(sb, evFork, 0);
    k_hist<<<NB_E4, 256, 0, sb>>>(ei);        // counts + ranks (single atomic/edge)
    k_blocksum<<<NB_N, 256, 0, sb>>>();       // coalesced block sums
    k_scatter2<<<NB_N, 256, 0, sb>>>();       // rowptr via lookback; re-zeroes g_cnt
    k_fill<<<NB_E4, 256, 0, sb>>>(ei);        // atomic-free via rank
    cudaEventRecord(evJoin, sb);

    // main stream
    k_prepack<<<3, 256>>>(Wl1, Wr1, Wl2, Wr2, mW1);
    k_gemm_tc<<<NB_G, 256>>>(x, Bp, Y, Z);                 // layer-1 pair
    cudaStreamWaitEvent(0, evJoin, 0);

    // layer-1 aggregate (2 warps/node) fused with layer-2 GEMM pair
    k_agg1_gemm2<<<NB_T, 1024>>>(Y, Z, bl1, g1, be1, m1, v1, Bp + 16384, Y2, Z2);
    // layer-2 aggregate (2 warps/node) fused with MLP head
    k_agg2_head<<<NB_T, 1024>>>(Y2, Z2, bl2, g2, be2, m2, v2, BpH, mb1, mW2, mb2, out);
}

// round 15
// speedup vs baseline: 1.3716x; 1.3716x over previous
#include <cuda_runtime.h>

#define N_NODES 100000
#define E_EDGES 1200000
#define DIM 64
#define EPS_BN 1e-5f
#define NB_N 391      // ceil(N_NODES/256)
#define NB_E8 586     // ceil(E_EDGES/2048)
#define NWARPS_G 6250 // N_NODES/16
#define NB_G 782      // ceil(6250/8)
#define NB_T 6250     // node-tile blocks (16 nodes each)
#define SH_STRIDE 68  // padded row stride (floats): conflict-free MMA A-reads

// ---------------- scratch (static device globals; no allocation) ----------------
__device__ int   g_cnt[N_NODES];        // zero at load; re-zeroed by k_scatter2 each launch
__device__ int   g_part[NB_N];
__device__ int   g_rowptr[N_NODES + 1];
__device__ int   g_rank[E_EDGES];
__device__ int   g_csr_src[E_EDGES];
__device__ float g_Y[(size_t)N_NODES * DIM];
__device__ float g_Z[(size_t)N_NODES * DIM];
__device__ float g_Y2[(size_t)N_NODES * DIM];
__device__ float g_Z2[(size_t)N_NODES * DIM];
// packed B fragments: [pair][ (nt*8+ks)*128 + lane*4 + {hi0,hi1,lo0,lo1} ]
__device__ float g_Bpack[2][16 * 8 * 32 * 4];
__device__ float g_BpackH[4 * 8 * 32 * 4];   // head W1 (32x64)

// ---------------- tf32 helpers ----------------
__device__ __forceinline__ unsigned cvt_tf32(float x) {
    unsigned r;
    asm("cvt.rna.tf32.f32 %0, %1;" : "=r"(r) : "f"(x));
    return r;
}
__device__ __forceinline__ void mma_tf32(float* c, const unsigned* a, unsigned b0, unsigned b1) {
    asm("mma.sync.aligned.m16n8k8.row.col.f32.tf32.tf32.f32 "
        "{%0,%1,%2,%3}, {%4,%5,%6,%7}, {%8,%9}, {%0,%1,%2,%3};"
        : "+f"(c[0]), "+f"(c[1]), "+f"(c[2]), "+f"(c[3])
        : "r"(a[0]), "r"(a[1]), "r"(a[2]), "r"(a[3]), "r"(b0), "r"(b1));
}

// ---------------- prepack W fragments (hi/lo tf32), parallel: 34 blocks ----------------
// blocks 0..31: layer pairs (16 blocks each, 256 idx per block)
// blocks 32..33: head W1 (512 idx per block)
__global__ __launch_bounds__(256) void k_prepack(const float* __restrict__ Wl1,
                                                 const float* __restrict__ Wr1,
                                                 const float* __restrict__ Wl2,
                                                 const float* __restrict__ Wr2,
                                                 const float* __restrict__ mW1) {
    int b = blockIdx.x;
    int t = threadIdx.x;
    if (b < 32) {
        int pair = b >> 4;
        const float* Wl = pair ? Wl2 : Wl1;
        const float* Wr = pair ? Wr2 : Wr1;
        int idx = (b & 15) * 256 + t;             // 0..4095
        int tile = idx >> 5, lane = idx & 31;
        int nt = tile >> 3, ks = tile & 7;
        int n = nt * 8 + (lane >> 2);
        int k = ks * 8 + (lane & 3);
        const float* W = (n < 64) ? Wl : Wr;
        int nn = n & 63;
        float w0 = W[nn * 64 + k];
        float w1 = W[nn * 64 + k + 4];
        unsigned h0 = cvt_tf32(w0), h1 = cvt_tf32(w1);
        unsigned l0 = cvt_tf32(w0 - __uint_as_float(h0));
        unsigned l1 = cvt_tf32(w1 - __uint_as_float(h1));
        ((float4*)(g_Bpack[pair]))[idx] =
            make_float4(__uint_as_float(h0), __uint_as_float(h1),
                        __uint_as_float(l0), __uint_as_float(l1));
    } else {
        int idx = (b - 32) * 512 + t;             // two blocks cover 1024
        if (t < 256 || idx < 1024) {
            if (idx < 1024) {
                int tile = idx >> 5, lane = idx & 31;
                int nt = tile >> 3, ks = tile & 7;
                int n = nt * 8 + (lane >> 2);
                int k = ks * 8 + (lane & 3);
                float w0 = mW1[n * 64 + k];
                float w1 = mW1[n * 64 + k + 4];
                unsigned h0 = cvt_tf32(w0), h1 = cvt_tf32(w1);
                unsigned l0 = cvt_tf32(w0 - __uint_as_float(h0));
                unsigned l1 = cvt_tf32(w1 - __uint_as_float(h1));
                ((float4*)g_BpackH)[idx] =
                    make_float4(__uint_as_float(h0), __uint_as_float(h1),
                                __uint_as_float(l0), __uint_as_float(l1));
            }
            if (idx + 256 < 1024) {
                int idx2 = idx + 256;
                int tile = idx2 >> 5, lane = idx2 & 31;
                int nt = tile >> 3, ks = tile & 7;
                int n = nt * 8 + (lane >> 2);
                int k = ks * 8 + (lane & 3);
                float w0 = mW1[n * 64 + k];
                float w1 = mW1[n * 64 + k + 4];
                unsigned h0 = cvt_tf32(w0), h1 = cvt_tf32(w1);
                unsigned l0 = cvt_tf32(w0 - __uint_as_float(h0));
                unsigned l1 = cvt_tf32(w1 - __uint_as_float(h1));
                ((float4*)g_BpackH)[idx2] =
                    make_float4(__uint_as_float(h0), __uint_as_float(h1),
                                __uint_as_float(l0), __uint_as_float(l1));
            }
        }
    }
}

// ---------------- layer-1 TC GEMM pair: [Y|Z] = X @ [Wl|Wr]^T, 3xTF32 ----------------
__global__ __launch_bounds__(256) void k_gemm_tc(const float* __restrict__ X,
                                                 const float* __restrict__ pack,
                                                 float* __restrict__ Y,
                                                 float* __restrict__ Z) {
    int w = (blockIdx.x * 256 + threadIdx.x) >> 5;
    int lane = threadIdx.x & 31;
    if (w >= NWARPS_G) return;

    int g = lane >> 2;
    int tg = lane & 3;
    int r0 = w * 16 + g;

    float c[16][4];
#pragma unroll
    for (int nt = 0; nt < 16; nt++) {
        c[nt][0] = 0.f; c[nt][1] = 0.f; c[nt][2] = 0.f; c[nt][3] = 0.f;
    }

    const float4* bp = (const float4*)pack;

#pragma unroll
    for (int ks = 0; ks < 8; ks++) {
        int k = ks * 8 + tg;
        float a00 = X[(size_t)r0 * 64 + k];
        float a10 = X[(size_t)(r0 + 8) * 64 + k];
        float a01 = X[(size_t)r0 * 64 + k + 4];
        float a11 = X[(size_t)(r0 + 8) * 64 + k + 4];

        unsigned ah[4], al[4];
        ah[0] = cvt_tf32(a00); al[0] = cvt_tf32(a00 - __uint_as_float(ah[0]));
        ah[1] = cvt_tf32(a10); al[1] = cvt_tf32(a10 - __uint_as_float(ah[1]));
        ah[2] = cvt_tf32(a01); al[2] = cvt_tf32(a01 - __uint_as_float(ah[2]));
        ah[3] = cvt_tf32(a11); al[3] = cvt_tf32(a11 - __uint_as_float(ah[3]));

#pragma unroll
        for (int nt = 0; nt < 16; nt++) {
            float4 b = bp[(nt * 8 + ks) * 32 + lane];
            mma_tf32(c[nt], ah, __float_as_uint(b.x), __float_as_uint(b.y));
            mma_tf32(c[nt], ah, __float_as_uint(b.z), __float_as_uint(b.w));
            mma_tf32(c[nt], al, __float_as_uint(b.x), __float_as_uint(b.y));
        }
    }

#pragma unroll
    for (int nt = 0; nt < 16; nt++) {
        int n0 = nt * 8 + 2 * tg;
        float* O = (nt < 8) ? Y : Z;
        int col = n0 & 63;
        ((float2*)(O + (size_t)r0 * 64 + col))[0] = make_float2(c[nt][0], c[nt][1]);
        ((float2*)(O + (size_t)(r0 + 8) * 64 + col))[0] = make_float2(c[nt][2], c[nt][3]);
    }
}

// ---------------- CSR build ----------------
// ILP-8 histogram; rank = atomicAdd return value (single atomic per edge)
__global__ __launch_bounds__(256) void k_hist(const int* __restrict__ ei) {
    int base = blockIdx.x * 2048 + threadIdx.x;
    int d[8], e[8];
#pragma unroll
    for (int u = 0; u < 8; u++) {
        e[u] = base + u * 256;
        d[u] = (e[u] < E_EDGES) ? ei[E_EDGES + e[u]] : -1;
    }
#pragma unroll
    for (int u = 0; u < 8; u++)
        if ((unsigned)d[u] < N_NODES)
            g_rank[e[u]] = atomicAdd(&g_cnt[d[u]], 1);
}

// per-block sums of 256 counters (coalesced reads, no atomics)
__global__ __launch_bounds__(256) void k_blocksum() {
    __shared__ int sc[256];
    int t = threadIdx.x;
    int i = blockIdx.x * 256 + t;
    int v = (i < N_NODES) ? g_cnt[i] : 0;
    sc[t] = v;
    __syncthreads();
    for (int off = 128; off > 0; off >>= 1) {
        if (t < off) sc[t] += sc[t + off];
        __syncthreads();
    }
    if (t == 0) g_part[blockIdx.x] = sc[0];
}

// scatter with inline lookback over g_part; also resets g_cnt for the next launch
__global__ __launch_bounds__(256) void k_scatter2() {
    __shared__ int sc[256];
    __shared__ int sbase[8];
    int t = threadIdx.x;
    int b = blockIdx.x;

    int acc = 0;
    for (int i = t; i < b; i += 256) acc += g_part[i];
#pragma unroll
    for (int o = 16; o > 0; o >>= 1) acc += __shfl_down_sync(0xffffffffu, acc, o);
    if ((t & 31) == 0) sbase[t >> 5] = acc;

    int i = b * 256 + t;
    int v = (i < N_NODES) ? g_cnt[i] : 0;
    sc[t] = v;
    __syncthreads();

    int base = 0;
#pragma unroll
    for (int w = 0; w < 8; w++) base += sbase[w];

    for (int off = 1; off < 256; off <<= 1) {
        int u = (t >= off) ? sc[t - off] : 0;
        __syncthreads();
        sc[t] += u;
        __syncthreads();
    }
    if (i < N_NODES) {
        g_rowptr[i] = base + sc[t] - v;
        g_cnt[i] = 0;   // self-clean: deterministic zero state for every launch
    }
    if (b == NB_N - 1 && t == 255) g_rowptr[N_NODES] = base + sc[255];
}

// atomic-free fill, ILP-8: pos = rowptr[dst] + rank
__global__ __launch_bounds__(256) void k_fill(const int* __restrict__ ei) {
    int base = blockIdx.x * 2048 + threadIdx.x;
    int s[8], d[8], r[8];
#pragma unroll
    for (int u = 0; u < 8; u++) {
        int e = base + u * 256;
        if (e < E_EDGES) { s[u] = ei[e]; d[u] = ei[E_EDGES + e]; r[u] = g_rank[e]; }
        else { s[u] = -1; d[u] = -1; r[u] = 0; }
    }
    int pos[8];
#pragma unroll
    for (int u = 0; u < 8; u++)
        pos[u] = ((unsigned)d[u] < N_NODES && (unsigned)s[u] < N_NODES)
                     ? (g_rowptr[d[u]] + r[u]) : -1;
#pragma unroll
    for (int u = 0; u < 8; u++)
        if (pos[u] >= 0) g_csr_src[pos[u]] = s[u];
}

// ---------------- gather body: mean-aggregate Y rows of node 'warp' ----------------
__device__ __forceinline__ void gather_body(const float* __restrict__ Y, int warp, int lane,
                                            float& ax, float& ay, float& inv) {
    int r0 = g_rowptr[warp];
    int r1 = g_rowptr[warp + 1];

    const float2* Y2 = (const float2*)Y;
    ax = 0.f; ay = 0.f;

    int e = r0;
    for (; e + 4 <= r1; e += 4) {
        int s0 = g_csr_src[e];
        int s1 = g_csr_src[e + 1];
        int s2 = g_csr_src[e + 2];
        int s3 = g_csr_src[e + 3];
        float2 v0 = Y2[(size_t)s0 * 32 + lane];
        float2 v1 = Y2[(size_t)s1 * 32 + lane];
        float2 v2 = Y2[(size_t)s2 * 32 + lane];
        float2 v3 = Y2[(size_t)s3 * 32 + lane];
        ax += (v0.x + v1.x) + (v2.x + v3.x);
        ay += (v0.y + v1.y) + (v2.y + v3.y);
    }
    if (e + 2 <= r1) {
        int s0 = g_csr_src[e];
        int s1 = g_csr_src[e + 1];
        float2 v0 = Y2[(size_t)s0 * 32 + lane];
        float2 v1 = Y2[(size_t)s1 * 32 + lane];
        ax += v0.x + v1.x;
        ay += v0.y + v1.y;
        e += 2;
    }
    if (e < r1) {
        float2 v = Y2[(size_t)g_csr_src[e] * 32 + lane];
        ax += v.x;
        ay += v.y;
    }
    int deg = r1 - r0;
    inv = 1.f / (float)(deg > 0 ? deg : 1);
}

// ---------------- BN+ReLU epilogue for lane's feature pair ----------------
__device__ __forceinline__ float2 bn_relu(float ax, float ay, float inv, int lane,
                                          const float* __restrict__ Z, int node,
                                          const float* __restrict__ bl,
                                          const float* __restrict__ gam,
                                          const float* __restrict__ bet,
                                          const float* __restrict__ mu,
                                          const float* __restrict__ var) {
    int j0 = 2 * lane, j1 = 2 * lane + 1;
    float2 z = ((const float2*)Z)[(size_t)node * 32 + lane];
    float h0 = ax * inv + bl[j0] + z.x;
    float h1 = ay * inv + bl[j1] + z.y;
    float s0 = gam[j0] * rsqrtf(var[j0] + EPS_BN);
    float s1 = gam[j1] * rsqrtf(var[j1] + EPS_BN);
    h0 = fmaxf((h0 - mu[j0]) * s0 + bet[j0], 0.f);
    h1 = fmaxf((h1 - mu[j1]) * s1 + bet[j1], 0.f);
    return make_float2(h0, h1);
}

// ---------------- fused: agg1 (BN1+ReLU) + layer-2 GEMM pair -> Y2, Z2 ----------------
__global__ __launch_bounds__(512) void k_agg1_gemm2(const float* __restrict__ Y,
                                                    const float* __restrict__ Z,
                                                    const float* __restrict__ bl,
                                                    const float* __restrict__ gam,
                                                    const float* __restrict__ bet,
                                                    const float* __restrict__ mu,
                                                    const float* __restrict__ var,
                                                    const float* __restrict__ pack,
                                                    float* __restrict__ Yo,
                                                    float* __restrict__ Zo) {
    __shared__ float sH[16 * SH_STRIDE];
    int tid = threadIdx.x;
    int wid = tid >> 5;
    int lane = tid & 31;
    int base = blockIdx.x * 16;
    int node = base + wid;

    float ax, ay, inv;
    gather_body(Y, node, lane, ax, ay, inv);
    float2 h = bn_relu(ax, ay, inv, lane, Z, node, bl, gam, bet, mu, var);
    ((float2*)(sH + wid * SH_STRIDE))[lane] = h;
    __syncthreads();

    // MMA phase: warp wid computes n-tile nt=wid over the 16-row tile
    int nt = wid;
    int g = lane >> 2;
    int tg = lane & 3;

    float c[4] = {0.f, 0.f, 0.f, 0.f};
    const float4* bp = (const float4*)pack;

#pragma unroll
    for (int ks = 0; ks < 8; ks++) {
        int k = ks * 8 + tg;
        float a00 = sH[g * SH_STRIDE + k];
        float a10 = sH[(g + 8) * SH_STRIDE + k];
        float a01 = sH[g * SH_STRIDE + k + 4];
        float a11 = sH[(g + 8) * SH_STRIDE + k + 4];

        unsigned ah[4], al[4];
        ah[0] = cvt_tf32(a00); al[0] = cvt_tf32(a00 - __uint_as_float(ah[0]));
        ah[1] = cvt_tf32(a10); al[1] = cvt_tf32(a10 - __uint_as_float(ah[1]));
        ah[2] = cvt_tf32(a01); al[2] = cvt_tf32(a01 - __uint_as_float(ah[2]));
        ah[3] = cvt_tf32(a11); al[3] = cvt_tf32(a11 - __uint_as_float(ah[3]));

        float4 b = bp[(nt * 8 + ks) * 32 + lane];
        mma_tf32(c, ah, __float_as_uint(b.x), __float_as_uint(b.y));
        mma_tf32(c, ah, __float_as_uint(b.z), __float_as_uint(b.w));
        mma_tf32(c, al, __float_as_uint(b.x), __float_as_uint(b.y));
    }

    float* O = (nt < 8) ? Yo : Zo;
    int col = (nt * 8 + 2 * tg) & 63;
    ((float2*)(O + (size_t)(base + g) * 64 + col))[0] = make_float2(c[0], c[1]);
    ((float2*)(O + (size_t)(base + g + 8) * 64 + col))[0] = make_float2(c[2], c[3]);
}

// ---------------- fused: agg2 (BN2+ReLU) + MLP head -> out ----------------
__global__ __launch_bounds__(512) void k_agg2_head(const float* __restrict__ Y,
                                                   const float* __restrict__ Z,
                                                   const float* __restrict__ bl,
                                                   const float* __restrict__ gam,
                                                   const float* __restrict__ bet,
                                                   const float* __restrict__ mu,
                                                   const float* __restrict__ var,
                                                   const float* __restrict__ packH,
                                                   const float* __restrict__ mb1,
                                                   const float* __restrict__ mW2,
                                                   const float* __restrict__ mb2,
                                                   float* __restrict__ out) {
    __shared__ float sH[16 * SH_STRIDE];
    __shared__ float spart[64];
    int tid = threadIdx.x;
    int wid = tid >> 5;
    int lane = tid & 31;
    int base = blockIdx.x * 16;
    int node = base + wid;

    float ax, ay, inv;
    gather_body(Y, node, lane, ax, ay, inv);
    float2 h = bn_relu(ax, ay, inv, lane, Z, node, bl, gam, bet, mu, var);
    ((float2*)(sH + wid * SH_STRIDE))[lane] = h;
    __syncthreads();

    if (wid < 4) {
        int nt = wid;
        int g = lane >> 2;
        int tg = lane & 3;

        float c[4] = {0.f, 0.f, 0.f, 0.f};
        const float4* bp = (const float4*)packH;

#pragma unroll
        for (int ks = 0; ks < 8; ks++) {
            int k = ks * 8 + tg;
            float a00 = sH[g * SH_STRIDE + k];
            float a10 = sH[(g + 8) * SH_STRIDE + k];
            float a01 = sH[g * SH_STRIDE + k + 4];
            float a11 = sH[(g + 8) * SH_STRIDE + k + 4];

            unsigned ah[4], al[4];
            ah[0] = cvt_tf32(a00); al[0] = cvt_tf32(a00 - __uint_as_float(ah[0]));
            ah[1] = cvt_tf32(a10); al[1] = cvt_tf32(a10 - __uint_as_float(ah[1]));
            ah[2] = cvt_tf32(a01); al[2] = cvt_tf32(a01 - __uint_as_float(ah[2]));
            ah[3] = cvt_tf32(a11); al[3] = cvt_tf32(a11 - __uint_as_float(ah[3]));

            float4 b = bp[(nt * 8 + ks) * 32 + lane];
            mma_tf32(c, ah, __float_as_uint(b.x), __float_as_uint(b.y));
            mma_tf32(c, ah, __float_as_uint(b.z), __float_as_uint(b.w));
            mma_tf32(c, al, __float_as_uint(b.x), __float_as_uint(b.y));
        }

        int j = nt * 8 + 2 * tg;
        float b1a = mb1[j], b1b = mb1[j + 1];
        float w2a = mW2[j], w2b = mW2[j + 1];
        float v0 = fmaxf(c[0] + b1a, 0.f) * w2a + fmaxf(c[1] + b1b, 0.f) * w2b;
        float v1 = fmaxf(c[2] + b1a, 0.f) * w2a + fmaxf(c[3] + b1b, 0.f) * w2b;
        v0 += __shfl_xor_sync(0xffffffffu, v0, 1);
        v0 += __shfl_xor_sync(0xffffffffu, v0, 2);
        v1 += __shfl_xor_sync(0xffffffffu, v1, 1);
        v1 += __shfl_xor_sync(0xffffffffu, v1, 2);
        int g2i = lane >> 2;
        if ((lane & 3) == 0) {
            spart[nt * 16 + g2i] = v0;
            spart[nt * 16 + g2i + 8] = v1;
        }
    }
    __syncthreads();

    if (tid < 16) {
        float s = spart[tid] + spart[16 + tid] + spart[32 + tid] + spart[48 + tid] + mb2[0];
        out[base + tid] = 1.f / (1.f + __expf(-s));
    }
}

// ---------------- launch ----------------
extern "C" void kernel_launch(void* const* d_in, const int* in_sizes, int n_in,
                              void* d_out, int out_size) {
    const float* x    = (const float*)d_in[0];
    const int*   ei   = (const int*)d_in[1];
    const float* Wl1  = (const float*)d_in[2];
    const float* bl1  = (const float*)d_in[3];
    const float* Wr1  = (const float*)d_in[4];
    const float* g1   = (const float*)d_in[5];
    const float* be1  = (const float*)d_in[6];
    const float* m1   = (const float*)d_in[7];
    const float* v1   = (const float*)d_in[8];
    const float* Wl2  = (const float*)d_in[9];
    const float* bl2  = (const float*)d_in[10];
    const float* Wr2  = (const float*)d_in[11];
    const float* g2   = (const float*)d_in[12];
    const float* be2  = (const float*)d_in[13];
    const float* m2   = (const float*)d_in[14];
    const float* v2   = (const float*)d_in[15];
    const float* mW1  = (const float*)d_in[16];
    const float* mb1  = (const float*)d_in[17];
    const float* mW2  = (const float*)d_in[18];
    const float* mb2  = (const float*)d_in[19];
    float* out = (float*)d_out;

    float* Y;  cudaGetSymbolAddress((void**)&Y, g_Y);
    float* Z;  cudaGetSymbolAddress((void**)&Z, g_Z);
    float* Y2; cudaGetSymbolAddress((void**)&Y2, g_Y2);
    float* Z2; cudaGetSymbolAddress((void**)&Z2, g_Z2);
    float* Bp; cudaGetSymbolAddress((void**)&Bp, g_Bpack);
    float* BpH; cudaGetSymbolAddress((void**)&BpH, g_BpackH);

    static cudaStream_t sb = nullptr;
    static cudaEvent_t evFork = nullptr, evJoin = nullptr;
    if (!sb) {
        cudaStreamCreateWithFlags(&sb, cudaStreamNonBlocking);
        cudaEventCreateWithFlags(&evFork, cudaEventDisableTiming);
        cudaEventCreateWithFlags(&evJoin, cudaEventDisableTiming);
    }

    // fork: CSR chain on side stream, concurrent with prepack + layer-1 GEMM
    cudaEventRecord(evFork, 0);
    cudaStreamWaitEvent(sb, evFork, 0);
    k_hist<<<NB_E8, 256, 0, sb>>>(ei);        // ILP-8: counts + ranks
    k_blocksum<<<NB_N, 256, 0, sb>>>();       // coalesced block sums
    k_scatter2<<<NB_N, 256, 0, sb>>>();       // rowptr via lookback; re-zeroes g_cnt
    k_fill<<<NB_E8, 256, 0, sb>>>(ei);        // ILP-8 atomic-free via rank
    cudaEventRecord(evJoin, sb);

    // main stream
    k_prepack<<<34, 256>>>(Wl1, Wr1, Wl2, Wr2, mW1);
    k_gemm_tc<<<NB_G, 256>>>(x, Bp, Y, Z);                 // layer-1 pair
    cudaStreamWaitEvent(0, evJoin, 0);

    // layer-1 aggregate fused with layer-2 GEMM pair
    k_agg1_gemm2<<<NB_T, 512>>>(Y, Z, bl1, g1, be1, m1, v1, Bp + 16384, Y2, Z2);
    // layer-2 aggregate fused with MLP head
    k_agg2_head<<<NB_T, 512>>>(Y2, Z2, bl2, g2, be2, m2, v2, BpH, mb1, mW2, mb2, out);
}